// round 2
// baseline (speedup 1.0000x reference)
#include <cuda_runtime.h>
#include <math.h>

typedef unsigned long long ull;

#define SS 512
#define NBLK 128

// ---------------- device scratch (no allocations allowed) ----------------
__device__ float g_WTenc[2048 * 4096];   // rows 0..1023 = enc_Wih^T, 1024..2047 = enc_Whh^T
__device__ float g_WTdec[2048 * 4096];   // same packing for decoder
__device__ float g_WTfc [1024 * 1024];   // fc_W^T
__device__ float g_gatesX[(size_t)64 * 512 * 4096]; // precomputed x@Wih^T for encoder (512MB)
__device__ float g_gatesW[2 * 64 * 4096];  // split-K partials of serial gate GEMM
__device__ float g_predW [8 * 64 * 1024];  // split-K partials of fc GEMM
__device__ float g_dA[64 * 2048];        // [b][0:1024]=decoder input, [b][1024:2048]=h
__device__ float g_c [64 * 1024];
__device__ int   g_mask[512];

__device__ unsigned           g_barCount;
__device__ volatile unsigned  g_barGen;

// ---------------- f32x2 helpers ----------------
__device__ __forceinline__ ull dup2(float v) {
    ull r; unsigned u = __float_as_uint(v);
    asm("mov.b64 %0, {%1, %1};" : "=l"(r) : "r"(u));
    return r;
}
__device__ __forceinline__ void fma2(ull& acc, ull a, ull b) {
    asm("fma.rn.f32x2 %0, %1, %2, %0;" : "+l"(acc) : "l"(a), "l"(b));
}
__device__ __forceinline__ float2 unpack2(ull v) {
    unsigned lo, hi;
    asm("mov.b64 {%0, %1}, %2;" : "=r"(lo), "=r"(hi) : "l"(v));
    return make_float2(__uint_as_float(lo), __uint_as_float(hi));
}
__device__ __forceinline__ float sigf(float x) { return 1.0f / (1.0f + expf(-x)); }

// ---------------- grid-wide barrier (all NBLK blocks co-resident) ----------------
__device__ __forceinline__ void grid_sync() {
    __syncthreads();
    if (threadIdx.x == 0) {
        __threadfence();
        unsigned gen = g_barGen;
        if (atomicAdd(&g_barCount, 1u) == NBLK - 1) {
            g_barCount = 0;
            __threadfence();
            g_barGen = gen + 1;
        } else {
            while (g_barGen == gen) { }
        }
        __threadfence();
    }
    __syncthreads();
}

// ============ standalone GEMM (pre-compute, 128 threads, 64x64 tile) ============
// C[m][n] = sum_k A[m][k] * W[k][n]
__global__ __launch_bounds__(128)
void gemm128(const float* __restrict__ A, int lda,
             const float* __restrict__ W, int ldw,
             float* __restrict__ C, int ldc, int K)
{
    __shared__ float As[32][66];
    __shared__ float Ws[32][64];

    const int tid   = threadIdx.x;
    const int nBase = blockIdx.x * 64;
    const int mBase = blockIdx.y * 64;

    const int tx = tid & 15;
    const int ty = tid >> 4;
    const int m0 = ty * 8;
    const int n0 = tx * 4;

    ull acc[4][4];
#pragma unroll
    for (int p = 0; p < 4; ++p)
#pragma unroll
        for (int n = 0; n < 4; ++n) acc[p][n] = 0ull;

    for (int kOff = 0; kOff < K; kOff += 32) {
#pragma unroll
        for (int i = 0; i < 4; ++i) {
            int idx = tid + i * 128;
            int m   = idx >> 3;
            int k4  = idx & 7;
            float4 v = *(const float4*)(A + (size_t)(mBase + m) * lda + kOff + k4 * 4);
            As[k4 * 4 + 0][m] = v.x;
            As[k4 * 4 + 1][m] = v.y;
            As[k4 * 4 + 2][m] = v.z;
            As[k4 * 4 + 3][m] = v.w;
        }
#pragma unroll
        for (int i = 0; i < 4; ++i) {
            int idx = tid + i * 128;
            int k   = idx >> 4;
            int n4  = idx & 15;
            *(float4*)&Ws[k][n4 * 4] =
                *(const float4*)(W + (size_t)(kOff + k) * ldw + nBase + n4 * 4);
        }
        __syncthreads();
#pragma unroll
        for (int kk = 0; kk < 32; ++kk) {
            const ull* ar = (const ull*)&As[kk][m0];
            ull a0 = ar[0], a1 = ar[1], a2 = ar[2], a3 = ar[3];
            float4 w = *(const float4*)&Ws[kk][n0];
            ull w0 = dup2(w.x), w1 = dup2(w.y), w2 = dup2(w.z), w3 = dup2(w.w);
            fma2(acc[0][0], a0, w0); fma2(acc[0][1], a0, w1);
            fma2(acc[0][2], a0, w2); fma2(acc[0][3], a0, w3);
            fma2(acc[1][0], a1, w0); fma2(acc[1][1], a1, w1);
            fma2(acc[1][2], a1, w2); fma2(acc[1][3], a1, w3);
            fma2(acc[2][0], a2, w0); fma2(acc[2][1], a2, w1);
            fma2(acc[2][2], a2, w2); fma2(acc[2][3], a2, w3);
            fma2(acc[3][0], a3, w0); fma2(acc[3][1], a3, w1);
            fma2(acc[3][2], a3, w2); fma2(acc[3][3], a3, w3);
        }
        __syncthreads();
    }
#pragma unroll
    for (int p = 0; p < 4; ++p) {
        int m = mBase + m0 + 2 * p;
#pragma unroll
        for (int n = 0; n < 4; ++n) {
            float2 v = unpack2(acc[p][n]);
            C[(size_t)m       * ldc + nBase + n0 + n] = v.x;
            C[(size_t)(m + 1) * ldc + nBase + n0 + n] = v.y;
        }
    }
}

// ============ in-kernel GEMM phase for the persistent kernel ============
// 256 threads, 64x64 output tile (M always 64), per-thread 8m x 2n as f32x2.
__device__ void gemm_block(const float* __restrict__ A, int lda,
                           const float* __restrict__ W, int ldw,
                           float* __restrict__ Cz, int ldc,
                           int nBase, int kOff0, int kLen,
                           float (*As)[66], float (*Ws)[64])
{
    const int tid = threadIdx.x;
    const int tx = tid & 31, ty = tid >> 5;
    const int m0 = ty * 8, n0 = tx * 2;

    ull acc[8];
#pragma unroll
    for (int i = 0; i < 8; ++i) acc[i] = 0ull;

    float4 pa[2], pw[2];
#pragma unroll
    for (int i = 0; i < 2; ++i) {
        int idx = tid + i * 256;
        pa[i] = *(const float4*)(A + (size_t)(idx >> 3) * lda + kOff0 + (idx & 7) * 4);
        pw[i] = *(const float4*)(W + (size_t)(kOff0 + (idx >> 4)) * ldw + nBase + (idx & 15) * 4);
    }

    for (int kt = 0; kt < kLen; kt += 32) {
#pragma unroll
        for (int i = 0; i < 2; ++i) {
            int idx = tid + i * 256;
            int m = idx >> 3, k4 = idx & 7;
            As[k4 * 4 + 0][m] = pa[i].x;
            As[k4 * 4 + 1][m] = pa[i].y;
            As[k4 * 4 + 2][m] = pa[i].z;
            As[k4 * 4 + 3][m] = pa[i].w;
            *(float4*)&Ws[idx >> 4][(idx & 15) * 4] = pw[i];
        }
        __syncthreads();
        if (kt + 32 < kLen) {
            int kOff = kOff0 + kt + 32;
#pragma unroll
            for (int i = 0; i < 2; ++i) {
                int idx = tid + i * 256;
                pa[i] = *(const float4*)(A + (size_t)(idx >> 3) * lda + kOff + (idx & 7) * 4);
                pw[i] = *(const float4*)(W + (size_t)(kOff + (idx >> 4)) * ldw + nBase + (idx & 15) * 4);
            }
        }
#pragma unroll
        for (int kk = 0; kk < 32; ++kk) {
            const ull* ar = (const ull*)&As[kk][m0];
            ull a0 = ar[0], a1 = ar[1], a2 = ar[2], a3 = ar[3];
            float2 wv = *(const float2*)&Ws[kk][n0];
            ull w0 = dup2(wv.x), w1 = dup2(wv.y);
            fma2(acc[0], a0, w0); fma2(acc[1], a0, w1);
            fma2(acc[2], a1, w0); fma2(acc[3], a1, w1);
            fma2(acc[4], a2, w0); fma2(acc[5], a2, w1);
            fma2(acc[6], a3, w0); fma2(acc[7], a3, w1);
        }
        __syncthreads();
    }
#pragma unroll
    for (int p = 0; p < 4; ++p) {
        float2 v0 = unpack2(acc[p * 2]);
        float2 v1 = unpack2(acc[p * 2 + 1]);
        int m = m0 + 2 * p;
        *(float2*)&Cz[(size_t)m       * ldc + nBase + n0] = make_float2(v0.x, v1.x);
        *(float2*)&Cz[(size_t)(m + 1) * ldc + nBase + n0] = make_float2(v0.y, v1.y);
    }
}

// ============ the persistent seq2seq kernel ============
__global__ __launch_bounds__(256, 1)
void seq2seq_persist(const float* __restrict__ x, const float* __restrict__ target,
                     const float* __restrict__ enc_b, const float* __restrict__ dec_b,
                     const float* __restrict__ fc_b, float* __restrict__ out)
{
    __shared__ float As[32][66];
    __shared__ float Ws[32][64];

    const int bid = blockIdx.x;
    const int tid = threadIdx.x;
    const int nt  = bid >> 1;   // gate GEMM n-tile (0..63)
    const int kz  = bid & 1;    // gate GEMM split-K slice
    const int ntf = bid >> 3;   // fc GEMM n-tile (0..15)
    const int kzf = bid & 7;    // fc GEMM split-K slice

    const float* WencH = g_WTenc + (size_t)1024 * 4096;   // Whh^T rows

    // ---------------- encoder ----------------
    for (int t = 0; t < SS; ++t) {
        // gates_hh = h @ Whh^T  (K=1024, split-K 2)
        gemm_block(g_dA + 1024, 2048, WencH, 4096,
                   g_gatesW + (size_t)kz * 64 * 4096, 4096,
                   nt * 64, kz * 512, 512, As, Ws);
        grid_sync();
        // cell: gates = bias + gatesX[t] + hh partials
#pragma unroll
        for (int r = 0; r < 2; ++r) {
            int i = bid * 512 + r * 256 + tid;       // 0..65535
            int b = i >> 10, j = i & 1023;
            const float* gx  = g_gatesX + ((size_t)b * SS + t) * 4096;
            const float* gw0 = g_gatesW + (size_t)b * 4096;
            const float* gw1 = g_gatesW + (size_t)64 * 4096 + (size_t)b * 4096;
            float gi = enc_b[j]        + gx[j]        + gw0[j]        + gw1[j];
            float gf = enc_b[j + 1024] + gx[j + 1024] + gw0[j + 1024] + gw1[j + 1024];
            float gg = enc_b[j + 2048] + gx[j + 2048] + gw0[j + 2048] + gw1[j + 2048];
            float go = enc_b[j + 3072] + gx[j + 3072] + gw0[j + 3072] + gw1[j + 3072];
            float c  = g_c[i];
            float cn = sigf(gf) * c + sigf(gi) * tanhf(gg);
            float hn = sigf(go) * tanhf(cn);
            g_c[i] = cn;
            g_dA[(size_t)b * 2048 + 1024 + j] = hn;
            if (t == SS - 1)   // stage dec_inp0 = x[:, -1, :]
                g_dA[(size_t)b * 2048 + j] = x[((size_t)b * SS + (SS - 1)) * 1024 + j];
        }
        grid_sync();
    }

    // ---------------- decoder ----------------
    for (int t = 0; t < SS; ++t) {
        // gates = [inp | h] @ WTdec   (K=2048, split-K 2)
        gemm_block(g_dA, 2048, g_WTdec, 4096,
                   g_gatesW + (size_t)kz * 64 * 4096, 4096,
                   nt * 64, kz * 1024, 1024, As, Ws);
        grid_sync();
#pragma unroll
        for (int r = 0; r < 2; ++r) {
            int i = bid * 512 + r * 256 + tid;
            int b = i >> 10, j = i & 1023;
            const float* gw0 = g_gatesW + (size_t)b * 4096;
            const float* gw1 = g_gatesW + (size_t)64 * 4096 + (size_t)b * 4096;
            float gi = dec_b[j]        + gw0[j]        + gw1[j];
            float gf = dec_b[j + 1024] + gw0[j + 1024] + gw1[j + 1024];
            float gg = dec_b[j + 2048] + gw0[j + 2048] + gw1[j + 2048];
            float go = dec_b[j + 3072] + gw0[j + 3072] + gw1[j + 3072];
            float c  = g_c[i];
            float cn = sigf(gf) * c + sigf(gi) * tanhf(gg);
            float hn = sigf(go) * tanhf(cn);
            g_c[i] = cn;
            g_dA[(size_t)b * 2048 + 1024 + j] = hn;
        }
        grid_sync();
        // pred partials = h @ fc_W^T  (K=1024, split-K 8)
        gemm_block(g_dA + 1024, 2048, g_WTfc, 1024,
                   g_predW + (size_t)kzf * 64 * 1024, 1024,
                   ntf * 64, kzf * 128, 128, As, Ws);
        grid_sync();
#pragma unroll
        for (int r = 0; r < 2; ++r) {
            int i = bid * 512 + r * 256 + tid;
            int b = i >> 10, n = i & 1023;
            float v = fc_b[n];
#pragma unroll
            for (int z = 0; z < 8; ++z)
                v += g_predW[(size_t)z * 64 * 1024 + (size_t)b * 1024 + n];
            size_t oidx = ((size_t)b * SS + t) * 1024 + n;
            out[oidx] = v;
            g_dA[(size_t)b * 2048 + n] = g_mask[t] ? target[oidx] : v;
        }
        grid_sync();
    }
}

// ---------------- transpose: dst[k*N + n] = src[n*K + k], src is (N, K) ----------------
__global__ void tposeK(float* __restrict__ dst, const float* __restrict__ src, int N, int K)
{
    __shared__ float t[32][33];
    int k0 = blockIdx.x * 32, n0 = blockIdx.y * 32;
#pragma unroll
    for (int i = 0; i < 32; i += 8)
        t[threadIdx.y + i][threadIdx.x] = src[(size_t)(n0 + threadIdx.y + i) * K + k0 + threadIdx.x];
    __syncthreads();
#pragma unroll
    for (int i = 0; i < 32; i += 8)
        dst[(size_t)(k0 + threadIdx.y + i) * N + n0 + threadIdx.x] = t[threadIdx.x][threadIdx.y + i];
}

// ---------------- tf_mask layout probe + decode ----------------
__global__ void mask_decode(const unsigned char* __restrict__ p)
{
    __shared__ int s_odd, s_big;
    int t = threadIdx.x;                 // 512 threads
    if (t == 0) { s_odd = 0; s_big = 0; }
    __syncthreads();
    unsigned char v = p[t];
    if ((t & 3) && v)  atomicOr(&s_odd, 1);
    if (v > 1)         atomicOr(&s_big, 1);
    __syncthreads();
    int m;
    if (s_big)        m = (((const float*)p)[t] != 0.0f);
    else if (s_odd)   m = (p[t] != 0);
    else              m = (((const int*)p)[t] != 0);
    g_mask[t] = m;
}

// ---------------- init: zero c and h, reset barrier ----------------
__global__ void init_state()
{
    int i = blockIdx.x * blockDim.x + threadIdx.x;   // 65536
    int b = i >> 10, j = i & 1023;
    g_c[i] = 0.0f;
    g_dA[(size_t)b * 2048 + 1024 + j] = 0.0f;
    if (i == 0) { g_barCount = 0; g_barGen = 0; }
}

// ---------------- host ----------------
extern "C" void kernel_launch(void* const* d_in, const int* in_sizes, int n_in,
                              void* d_out, int out_size)
{
    (void)in_sizes; (void)n_in; (void)out_size;
    const float* x       = (const float*)d_in[0];
    const float* target  = (const float*)d_in[1];
    const float* enc_Wih = (const float*)d_in[2];
    const float* enc_Whh = (const float*)d_in[3];
    const float* enc_b   = (const float*)d_in[4];
    const float* dec_Wih = (const float*)d_in[5];
    const float* dec_Whh = (const float*)d_in[6];
    const float* dec_b   = (const float*)d_in[7];
    const float* fc_W    = (const float*)d_in[8];
    const float* fc_b    = (const float*)d_in[9];
    const unsigned char* tf_mask = (const unsigned char*)d_in[10];
    float* out = (float*)d_out;

    float *pWTenc, *pWTdec, *pWTfc, *pGatesX;
    cudaGetSymbolAddress((void**)&pWTenc,  g_WTenc);
    cudaGetSymbolAddress((void**)&pWTdec,  g_WTdec);
    cudaGetSymbolAddress((void**)&pWTfc,   g_WTfc);
    cudaGetSymbolAddress((void**)&pGatesX, g_gatesX);

    mask_decode<<<1, 512>>>(tf_mask);

    dim3 tb(32, 8);
    tposeK<<<dim3(32, 128), tb>>>(pWTenc,                       enc_Wih, 4096, 1024);
    tposeK<<<dim3(32, 128), tb>>>(pWTenc + (size_t)1024 * 4096, enc_Whh, 4096, 1024);
    tposeK<<<dim3(32, 128), tb>>>(pWTdec,                       dec_Wih, 4096, 1024);
    tposeK<<<dim3(32, 128), tb>>>(pWTdec + (size_t)1024 * 4096, dec_Whh, 4096, 1024);
    tposeK<<<dim3(32, 32),  tb>>>(pWTfc,                        fc_W,    1024, 1024);

    init_state<<<256, 256>>>();

    // Precompute encoder input-gate contributions for ALL timesteps:
    // gatesX[(b*512+t)][4096] = x[b,t,:] @ enc_Wih^T   (M=32768, K=1024, N=4096)
    gemm128<<<dim3(64, 512), 128>>>(x, 1024, pWTenc, 4096, pGatesX, 4096, 1024);

    // One persistent kernel for the full recurrence (128 co-resident blocks).
    seq2seq_persist<<<NBLK, 256>>>(x, target, enc_b, dec_b, fc_b, out);
}